// round 10
// baseline (speedup 1.0000x reference)
#include <cuda_runtime.h>

#define W_      10
#define NSTATE  4096
#define BATCH   512
#define NIN     6
#define STAGES  2

typedef unsigned long long u64;

#define NEGB   0x8000000080000000ULL
#define MASKP  0x0000000080000000ULL   // negate lo lane
#define MASKM  0x8000000000000000ULL   // negate hi lane

// Packed tables: per entry {cc=(c,c), nss=(-s,-s)}
__device__ ulonglong2 g_tabP[STAGES * W_ * 1024];
__device__ ulonglong2 u_tabP[STAGES * W_];

__global__ void precompute_kernel(const float* __restrict__ unitary_theta,
                                  const float* __restrict__ neuron_theta) {
    int idx = blockIdx.x * blockDim.x + threadIdx.x;
    if (idx < STAGES * W_ * 1024) {
        int g  = idx & 1023;
        int sn = idx >> 10;
        const float* th = neuron_theta + sn * (W_ + 1);
        float phi = th[W_];
        #pragma unroll
        for (int i = 0; i < W_; i++)
            if ((g >> (9 - i)) & 1) phi += th[i];
        float sv, cv;
        sincosf(phi * 0.5f, &sv, &cv);
        float2 cc = make_float2(cv, cv);
        float2 ns = make_float2(-sv, -sv);
        g_tabP[idx] = make_ulonglong2(*(u64*)&cc, *(u64*)&ns);
    }
    if (idx < STAGES * W_) {
        float sv, cv;
        sincosf(unitary_theta[idx] * 0.5f, &sv, &cv);
        float2 cc = make_float2(cv, cv);
        float2 ns = make_float2(-sv, -sv);
        u_tabP[idx] = make_ulonglong2(*(u64*)&cc, *(u64*)&ns);
    }
}

// ---- f32x2 primitives (asm forms — R7-proven, no local-memory traps) ----
__device__ __forceinline__ u64 f2mul(u64 a, u64 b) {
    u64 r; asm("mul.rn.f32x2 %0, %1, %2;" : "=l"(r) : "l"(a), "l"(b)); return r;
}
__device__ __forceinline__ u64 f2fma(u64 a, u64 b, u64 c) {
    u64 r; asm("fma.rn.f32x2 %0, %1, %2, %3;" : "=l"(r) : "l"(a), "l"(b), "l"(c)); return r;
}
__device__ __forceinline__ u64 lswap(u64 a) {
    u64 r; asm("{.reg .b32 x,y; mov.b64 {x,y}, %1; mov.b64 %0, {y,x};}" : "=l"(r) : "l"(a)); return r;
}
// A.hi_new = -B.hi_old ; B.hi_new = A.hi_old
__device__ __forceinline__ void xswapneg(u64& a, u64& b) {
    asm("{\n\t.reg .b32 al,ah,bl,bh;\n\t"
        "mov.b64 {al,ah}, %0;\n\t"
        "mov.b64 {bl,bh}, %1;\n\t"
        "neg.f32 bh, bh;\n\t"
        "mov.b64 %0, {al,bh};\n\t"
        "mov.b64 %1, {bl,ah};\n\t}"
        : "+l"(a), "+l"(b));
}

// ---- swizzle on float4-group index (R7-proven conflict-free) ----
__device__ __forceinline__ int swG(int G) {
    return G ^ ( ((G >> 3) & 1)
               | (((G >> 4) & 1) << 1)
               | ((((G >> 5) ^ (G >> 4)) & 1) << 2) );
}
__device__ __forceinline__ int swE(int e) { return (swG(e >> 1) << 1) | (e & 1); }

__device__ __forceinline__ void ld2(const u64* sm, int g, u64& a, u64& b) {
    ulonglong2 v = *(const ulonglong2*)(sm + (swG(g) << 1)); a = v.x; b = v.y;
}
__device__ __forceinline__ void st2(u64* sm, int g, u64 a, u64 b) {
    *(ulonglong2*)(sm + (swG(g) << 1)) = make_ulonglong2(a, b);
}

// grp4p: RY(+phi) q10, CRY(sgn*pi) 10->11, RY(-phi) q10
__device__ __forceinline__ void grp4p(u64& qxy, u64& qzw,
                                      u64 cc, u64 ss, u64 nss, u64 umask) {
    u64 t01 = f2fma(cc, qxy, f2mul(nss, qzw));
    u64 t23 = f2fma(cc, qzw, f2mul(ss,  qxy));
    u64 u23 = lswap(t23) ^ umask;
    qxy = f2fma(cc, t01, f2mul(ss,  u23));
    qzw = f2fma(cc, u23, f2mul(nss, t01));
}
// full neuron on 8 amps; coefficients arrive packed {cc, nss}
__device__ __forceinline__ void neuron8p(u64& xy0, u64& zw0, u64& xy1, u64& zw1,
                                         ulonglong2 T0, ulonglong2 T1) {
    u64 cc0 = T0.x, nss0 = T0.y, ss0 = nss0 ^ NEGB;
    u64 cc1 = T1.x, nss1 = T1.y, ss1 = nss1 ^ NEGB;
    grp4p(xy0, zw0, cc0, ss0, nss0, MASKP);
    grp4p(xy1, zw1, cc1, ss1, nss1, MASKP);
    xswapneg(xy0, xy1);
    xswapneg(zw0, zw1);
    grp4p(xy0, zw0, cc0, ss0, nss0, MASKM);
    grp4p(xy1, zw1, cc1, ss1, nss1, MASKM);
}

// RY on bit `bit` of the 8-element u64 register index
__device__ __forceinline__ void ry8b(u64 R[8], int bit, ulonglong2 T) {
    u64 cc = T.x, nss = T.y, ss = nss ^ NEGB;
    #pragma unroll
    for (int k = 0; k < 8; k++) {
        if (!((k >> bit) & 1)) {
            int k1 = k | (1 << bit);
            u64 a = R[k], b2 = R[k1];
            R[k]  = f2fma(cc, a, f2mul(nss, b2));
            R[k1] = f2fma(ss, a, f2mul(cc,  b2));
        }
    }
}

// Neuron pair: neurons targeting amp bits PA, PA-1; thread owns amp bits {PA,PA-1,1,0}
template <int PA>
__device__ __forceinline__ void neuron_pairp(u64* sm,
                                             const ulonglong2* __restrict__ tabA,
                                             const ulonglong2* __restrict__ tabB,
                                             int t) {
    constexpr int PB = PA - 1;
    constexpr int LB = PB - 2;
    const int low  = t & ((1 << LB) - 1);
    const int high = t >> LB;
    const int gb   = low | (high << (PA - 1));

    const int g00 = gb;
    const int g01 = gb + (1 << (PB - 2));
    const int g10 = gb + (1 << (PA - 2));
    const int g11 = g10 + (1 << (PB - 2));

    u64 a0, b0, a1, b1, a2, b2, a3, b3;
    ld2(sm, g00, a0, b0); ld2(sm, g01, a1, b1);
    ld2(sm, g10, a2, b2); ld2(sm, g11, a3, b3);

    neuron8p(a0, b0, a2, b2, tabA[g00], tabA[g10]);
    neuron8p(a1, b1, a3, b3, tabA[g01], tabA[g11]);
    neuron8p(a0, b0, a1, b1, tabB[g00], tabB[g01]);
    neuron8p(a2, b2, a3, b3, tabB[g10], tabB[g11]);

    st2(sm, g00, a0, b0); st2(sm, g01, a1, b1);
    st2(sm, g10, a2, b2); st2(sm, g11, a3, b3);
}

__global__ void __launch_bounds__(256, 4) sim_kernel(
    const float* __restrict__ psi_in,
    const int*   __restrict__ inp,
    float*       __restrict__ probs_out,
    float*       __restrict__ psi_out)
{
    __shared__ __align__(16) u64 sm[NSTATE / 2];
    __shared__ float red[256];

    const int b = blockIdx.x;
    const int t = threadIdx.x;

    int mask = 0;
    #pragma unroll
    for (int l = 0; l < NIN; l++) mask |= (inp[l] & 1) << (11 - l);

    #pragma unroll
    for (int s = 0; s < STAGES; s++) {
        const ulonglong2* ut = &u_tabP[s * W_];

        // ---- U-A: RY lanes 0,1,2 (e bits 10,9,8). e = t | (k<<8).
        {
            u64 R[8];
            if (s == 0) {
                const float* in = psi_in + (size_t)b * NSTATE;
                #pragma unroll
                for (int k = 0; k < 8; k++) {
                    int e = t | (k << 8);
                    R[k] = *(const u64*)(in + ((e << 1) ^ mask));
                }
            } else {
                #pragma unroll
                for (int k = 0; k < 8; k++) R[k] = sm[swE(t | (k << 8))];
            }
            ry8b(R, 2, ut[0]); ry8b(R, 1, ut[1]); ry8b(R, 0, ut[2]);
            #pragma unroll
            for (int k = 0; k < 8; k++) sm[swE(t | (k << 8))] = R[k];
        }
        __syncthreads();

        // ---- U-B: RY lanes 3,4,5 (e bits 7,6,5). Warp-local: e in [256w, 256w+255].
        {
            const int base = (t & 31) | ((t >> 5) << 8);
            u64 R[8];
            #pragma unroll
            for (int k = 0; k < 8; k++) R[k] = sm[swE(base | (k << 5))];
            ry8b(R, 2, ut[3]); ry8b(R, 1, ut[4]); ry8b(R, 0, ut[5]);
            #pragma unroll
            for (int k = 0; k < 8; k++) sm[swE(base | (k << 5))] = R[k];
        }
        __syncwarp();   // U-C reads only this warp's 256-amp span

        // ---- U-C: RY lanes 6,7,8 (e bits 4,3,2) + lane 9 (e bit 1) via shfl.
        {
            const int base = (t & 3) | ((t >> 2) << 5);
            u64 R[8];
            #pragma unroll
            for (int k = 0; k < 8; k++) R[k] = sm[swE(base | (k << 2))];
            ry8b(R, 2, ut[6]); ry8b(R, 1, ut[7]); ry8b(R, 0, ut[8]);
            {
                ulonglong2 T9 = ut[9];
                u64 cc = T9.x;
                u64 sp = (t & 2) ? (T9.y ^ NEGB) : T9.y;   // +s if e-bit1==1 else -s
                #pragma unroll
                for (int k = 0; k < 8; k++) {
                    u64 o = __shfl_xor_sync(0xffffffffu, R[k], 2);
                    R[k] = f2fma(cc, R[k], f2mul(sp, o));
                }
            }
            #pragma unroll
            for (int k = 0; k < 8; k++) sm[swE(base | (k << 2))] = R[k];
        }
        __syncthreads();

        const ulonglong2* tb = &g_tabP[(s * W_) << 10];

        // ---- neuron pairs
        neuron_pairp<11>(sm, tb + (0 << 10), tb + (1 << 10), t); __syncthreads();
        neuron_pairp<9 >(sm, tb + (2 << 10), tb + (3 << 10), t); __syncthreads();
        neuron_pairp<7 >(sm, tb + (4 << 10), tb + (5 << 10), t); __syncwarp();  // G in [128w,128w+127]
        neuron_pairp<5 >(sm, tb + (6 << 10), tb + (7 << 10), t); __syncwarp();  // same warp block

        // ---- neurons 8,9 (group bits 1,0): 4 contiguous groups (warp-local reads).
        {
            const ulonglong2* tabA = tb + (8 << 10);
            const ulonglong2* tabB = tb + (9 << 10);
            const int G0 = t << 2;
            u64 a0, b0, a1, b1, a2, b2, a3, b3;
            ld2(sm, G0,     a0, b0); ld2(sm, G0 + 1, a1, b1);
            ld2(sm, G0 + 2, a2, b2); ld2(sm, G0 + 3, a3, b3);

            neuron8p(a0, b0, a2, b2, tabA[G0],     tabA[G0 + 2]);
            neuron8p(a1, b1, a3, b3, tabA[G0 + 1], tabA[G0 + 3]);
            neuron8p(a0, b0, a1, b1, tabB[G0],     tabB[G0 + 1]);
            neuron8p(a2, b2, a3, b3, tabB[G0 + 2], tabB[G0 + 3]);

            if (s == STAGES - 1) {
                ulonglong2* out2 = (ulonglong2*)(psi_out + (size_t)b * NSTATE);
                out2[G0]     = make_ulonglong2(a0, b0);
                out2[G0 + 1] = make_ulonglong2(a1, b1);
                out2[G0 + 2] = make_ulonglong2(a2, b2);
                out2[G0 + 3] = make_ulonglong2(a3, b3);
                u64 q[8] = {a0, b0, a1, b1, a2, b2, a3, b3};
                float ssq = 0.f;
                #pragma unroll
                for (int j = 0; j < 8; j++) {
                    float2 f = *(float2*)&q[j];
                    ssq += f.x * f.x + f.y * f.y;
                }
                red[t] = ssq;
            } else {
                st2(sm, G0,     a0, b0); st2(sm, G0 + 1, a1, b1);
                st2(sm, G0 + 2, a2, b2); st2(sm, G0 + 3, a3, b3);
            }
        }
        __syncthreads();
    }

    if (t < 64) {
        probs_out[b * 64 + t] =
            red[4 * t] + red[4 * t + 1] + red[4 * t + 2] + red[4 * t + 3];
    }
}

extern "C" void kernel_launch(void* const* d_in, const int* in_sizes, int n_in,
                              void* d_out, int out_size) {
    const float* psi = (const float*)d_in[0];
    const int*   inp = (const int*)d_in[1];
    const float* uth = (const float*)d_in[2];
    const float* nth = (const float*)d_in[3];
    float* out = (float*)d_out;

    float* probs_out = out;
    float* psi_out   = out + BATCH * 64;

    precompute_kernel<<<(STAGES * W_ * 1024 + 255) / 256, 256>>>(uth, nth);
    sim_kernel<<<BATCH, 256>>>(psi, inp, probs_out, psi_out);
}

// round 11
// speedup vs baseline: 1.1979x; 1.1979x over previous
#include <cuda_runtime.h>

#define W_      10
#define NSTATE  4096
#define BATCH   512
#define NIN     6
#define STAGES  2

typedef unsigned long long u64;

#define NEGB   0x8000000080000000ULL
#define MASKP  0x0000000080000000ULL
#define MASKM  0x8000000000000000ULL

// g_tab[(s*W + out)*1024 + g] = (cos(phi/2), sin(phi/2)); g = amp bits 11..2
__device__ float2 g_tab[STAGES * W_ * 1024];
__device__ float2 u_tab[STAGES * W_];

__global__ void precompute_kernel(const float* __restrict__ unitary_theta,
                                  const float* __restrict__ neuron_theta) {
    int idx = blockIdx.x * blockDim.x + threadIdx.x;
    if (idx < STAGES * W_ * 1024) {
        int g  = idx & 1023;
        int sn = idx >> 10;
        const float* th = neuron_theta + sn * (W_ + 1);
        float phi = th[W_];
        #pragma unroll
        for (int i = 0; i < W_; i++)
            if ((g >> (9 - i)) & 1) phi += th[i];
        float sv, cv;
        sincosf(phi * 0.5f, &sv, &cv);
        g_tab[idx] = make_float2(cv, sv);
    }
    if (idx < STAGES * W_) {
        float sv, cv;
        sincosf(unitary_theta[idx] * 0.5f, &sv, &cv);
        u_tab[idx] = make_float2(cv, sv);
    }
}

// ---- f32x2 primitives ----
__device__ __forceinline__ u64 pk2(float lo, float hi) {
    u64 r; asm("mov.b64 %0, {%1,%2};" : "=l"(r) : "f"(lo), "f"(hi)); return r;
}
__device__ __forceinline__ u64 bcast(float v) { return pk2(v, v); }
__device__ __forceinline__ u64 f2mul(u64 a, u64 b) {
    u64 r; asm("mul.rn.f32x2 %0, %1, %2;" : "=l"(r) : "l"(a), "l"(b)); return r;
}
__device__ __forceinline__ u64 f2fma(u64 a, u64 b, u64 c) {
    u64 r; asm("fma.rn.f32x2 %0, %1, %2, %3;" : "=l"(r) : "l"(a), "l"(b), "l"(c)); return r;
}
__device__ __forceinline__ u64 lswap(u64 a) {
    u64 r; asm("{.reg .b32 x,y; mov.b64 {x,y}, %1; mov.b64 %0, {y,x};}" : "=l"(r) : "l"(a)); return r;
}
// A.hi_new = -B.hi_old ; B.hi_new = A.hi_old
__device__ __forceinline__ void xswapneg(u64& a, u64& b) {
    asm("{\n\t.reg .b32 al,ah,bl,bh;\n\t"
        "mov.b64 {al,ah}, %0;\n\t"
        "mov.b64 {bl,bh}, %1;\n\t"
        "neg.f32 bh, bh;\n\t"
        "mov.b64 %0, {al,bh};\n\t"
        "mov.b64 %1, {bl,ah};\n\t}"
        : "+l"(a), "+l"(b));
}

// ---- swizzle on float4-group index (proven conflict-free) ----
__device__ __forceinline__ int swG(int G) {
    return G ^ ( ((G >> 3) & 1)
               | (((G >> 4) & 1) << 1)
               | ((((G >> 5) ^ (G >> 4)) & 1) << 2) );
}
__device__ __forceinline__ int swE(int e) { return (swG(e >> 1) << 1) | (e & 1); }

__device__ __forceinline__ void ld2(const u64* sm, int g, u64& a, u64& b) {
    ulonglong2 v = *(const ulonglong2*)(sm + (swG(g) << 1)); a = v.x; b = v.y;
}
__device__ __forceinline__ void st2(u64* sm, int g, u64 a, u64 b) {
    *(ulonglong2*)(sm + (swG(g) << 1)) = make_ulonglong2(a, b);
}

// grp4p: RY(+phi) q10, CRY(sgn*pi) 10->11, RY(-phi) q10
__device__ __forceinline__ void grp4p(u64& qxy, u64& qzw,
                                      u64 cc, u64 ss, u64 nss, u64 umask) {
    u64 t01 = f2fma(cc, qxy, f2mul(nss, qzw));
    u64 t23 = f2fma(cc, qzw, f2mul(ss,  qxy));
    u64 u23 = lswap(t23) ^ umask;
    qxy = f2fma(cc, t01, f2mul(ss,  u23));
    qzw = f2fma(cc, u23, f2mul(nss, t01));
}
// full neuron on 8 amps (two packed groups)
__device__ __forceinline__ void neuron8p(u64& xy0, u64& zw0, u64& xy1, u64& zw1,
                                         float2 cs0, float2 cs1) {
    u64 cc0 = bcast(cs0.x), ss0 = bcast(cs0.y), nss0 = ss0 ^ NEGB;
    u64 cc1 = bcast(cs1.x), ss1 = bcast(cs1.y), nss1 = ss1 ^ NEGB;
    grp4p(xy0, zw0, cc0, ss0, nss0, MASKP);
    grp4p(xy1, zw1, cc1, ss1, nss1, MASKP);
    xswapneg(xy0, xy1);
    xswapneg(zw0, zw1);
    grp4p(xy0, zw0, cc0, ss0, nss0, MASKM);
    grp4p(xy1, zw1, cc1, ss1, nss1, MASKM);
}

// RY on bit `bit` of the 8-element u64 register index
__device__ __forceinline__ void ry8b(u64 R[8], int bit, float2 cs) {
    u64 cc = bcast(cs.x), ss = bcast(cs.y), nss = ss ^ NEGB;
    #pragma unroll
    for (int k = 0; k < 8; k++) {
        if (!((k >> bit) & 1)) {
            int k1 = k | (1 << bit);
            u64 a = R[k], b2 = R[k1];
            R[k]  = f2fma(cc, a, f2mul(nss, b2));
            R[k1] = f2fma(ss, a, f2mul(cc,  b2));
        }
    }
}

// Neuron pair: neurons targeting amp bits PA, PA-1; thread owns amp bits {PA,PA-1,1,0}
template <int PA>
__device__ __forceinline__ void neuron_pairp(u64* sm,
                                             const float2* __restrict__ tabA,
                                             const float2* __restrict__ tabB,
                                             int t) {
    constexpr int PB = PA - 1;
    constexpr int LB = PB - 2;
    const int low  = t & ((1 << LB) - 1);
    const int high = t >> LB;
    const int gb   = low | (high << (PA - 1));

    const int g00 = gb;
    const int g01 = gb + (1 << (PB - 2));
    const int g10 = gb + (1 << (PA - 2));
    const int g11 = g10 + (1 << (PB - 2));

    u64 a0, b0, a1, b1, a2, b2, a3, b3;
    ld2(sm, g00, a0, b0); ld2(sm, g01, a1, b1);
    ld2(sm, g10, a2, b2); ld2(sm, g11, a3, b3);

    neuron8p(a0, b0, a2, b2, tabA[g00], tabA[g10]);
    neuron8p(a1, b1, a3, b3, tabA[g01], tabA[g11]);
    neuron8p(a0, b0, a1, b1, tabB[g00], tabB[g01]);
    neuron8p(a2, b2, a3, b3, tabB[g10], tabB[g11]);

    st2(sm, g00, a0, b0); st2(sm, g01, a1, b1);
    st2(sm, g10, a2, b2); st2(sm, g11, a3, b3);
}

__global__ void __launch_bounds__(256, 4) sim_kernel(
    const float* __restrict__ psi_in,
    const int*   __restrict__ inp,
    float*       __restrict__ probs_out,
    float*       __restrict__ psi_out)
{
    __shared__ __align__(16) u64 sm[NSTATE / 2];
    __shared__ float red[256];

    const int b = blockIdx.x;
    const int t = threadIdx.x;

    int mask = 0;
    #pragma unroll
    for (int l = 0; l < NIN; l++) mask |= (inp[l] & 1) << (11 - l);

    #pragma unroll
    for (int s = 0; s < STAGES; s++) {
        const float2* ut = &u_tab[s * W_];

        // ---- U-A: RY lanes 0,1,2 (e bits 10,9,8). e = t | (k<<8).
        {
            u64 R[8];
            if (s == 0) {
                const float* in = psi_in + (size_t)b * NSTATE;
                #pragma unroll
                for (int k = 0; k < 8; k++) {
                    int e = t | (k << 8);
                    R[k] = *(const u64*)(in + ((e << 1) ^ mask));
                }
            } else {
                #pragma unroll
                for (int k = 0; k < 8; k++) R[k] = sm[swE(t | (k << 8))];
            }
            ry8b(R, 2, ut[0]); ry8b(R, 1, ut[1]); ry8b(R, 0, ut[2]);
            #pragma unroll
            for (int k = 0; k < 8; k++) sm[swE(t | (k << 8))] = R[k];
        }
        __syncthreads();

        // ---- U-B: RY lanes 3,4,5 (e bits 7,6,5). Warp-local: e in [256w, 256w+255].
        {
            const int base = (t & 31) | ((t >> 5) << 8);
            u64 R[8];
            #pragma unroll
            for (int k = 0; k < 8; k++) R[k] = sm[swE(base | (k << 5))];
            ry8b(R, 2, ut[3]); ry8b(R, 1, ut[4]); ry8b(R, 0, ut[5]);
            #pragma unroll
            for (int k = 0; k < 8; k++) sm[swE(base | (k << 5))] = R[k];
        }
        __syncwarp();   // U-C reads only this warp's 256-amp span

        // ---- U-C: RY lanes 6,7,8 (e bits 4,3,2) + lane 9 (e bit 1) via shfl.
        {
            const int base = (t & 3) | ((t >> 2) << 5);
            u64 R[8];
            #pragma unroll
            for (int k = 0; k < 8; k++) R[k] = sm[swE(base | (k << 2))];
            ry8b(R, 2, ut[6]); ry8b(R, 1, ut[7]); ry8b(R, 0, ut[8]);
            {
                u64 cc = bcast(ut[9].x);
                u64 sp = bcast((t & 2) ? ut[9].y : -ut[9].y);
                #pragma unroll
                for (int k = 0; k < 8; k++) {
                    u64 o = __shfl_xor_sync(0xffffffffu, R[k], 2);
                    R[k] = f2fma(cc, R[k], f2mul(sp, o));
                }
            }
            #pragma unroll
            for (int k = 0; k < 8; k++) sm[swE(base | (k << 2))] = R[k];
        }
        __syncthreads();

        const float2* tb = &g_tab[(s * W_) << 10];

        // ---- neuron pairs
        neuron_pairp<11>(sm, tb + (0 << 10), tb + (1 << 10), t); __syncthreads();
        neuron_pairp<9 >(sm, tb + (2 << 10), tb + (3 << 10), t); __syncthreads();
        neuron_pairp<7 >(sm, tb + (4 << 10), tb + (5 << 10), t); __syncwarp();  // G in [128w,128w+127]
        neuron_pairp<5 >(sm, tb + (6 << 10), tb + (7 << 10), t); __syncwarp();  // same warp block

        // ---- neurons 8,9 (group bits 1,0): 4 contiguous groups (warp-local reads).
        {
            const float2* tabA = tb + (8 << 10);
            const float2* tabB = tb + (9 << 10);
            const int G0 = t << 2;
            u64 a0, b0, a1, b1, a2, b2, a3, b3;
            ld2(sm, G0,     a0, b0); ld2(sm, G0 + 1, a1, b1);
            ld2(sm, G0 + 2, a2, b2); ld2(sm, G0 + 3, a3, b3);

            neuron8p(a0, b0, a2, b2, tabA[G0],     tabA[G0 + 2]);
            neuron8p(a1, b1, a3, b3, tabA[G0 + 1], tabA[G0 + 3]);
            neuron8p(a0, b0, a1, b1, tabB[G0],     tabB[G0 + 1]);
            neuron8p(a2, b2, a3, b3, tabB[G0 + 2], tabB[G0 + 3]);

            if (s == STAGES - 1) {
                ulonglong2* out2 = (ulonglong2*)(psi_out + (size_t)b * NSTATE);
                out2[G0]     = make_ulonglong2(a0, b0);
                out2[G0 + 1] = make_ulonglong2(a1, b1);
                out2[G0 + 2] = make_ulonglong2(a2, b2);
                out2[G0 + 3] = make_ulonglong2(a3, b3);
                u64 q[8] = {a0, b0, a1, b1, a2, b2, a3, b3};
                float ssq = 0.f;
                #pragma unroll
                for (int j = 0; j < 8; j++) {
                    float2 f = *(float2*)&q[j];
                    ssq += f.x * f.x + f.y * f.y;
                }
                red[t] = ssq;
            } else {
                st2(sm, G0,     a0, b0); st2(sm, G0 + 1, a1, b1);
                st2(sm, G0 + 2, a2, b2); st2(sm, G0 + 3, a3, b3);
            }
        }
        __syncthreads();
    }

    if (t < 64) {
        probs_out[b * 64 + t] =
            red[4 * t] + red[4 * t + 1] + red[4 * t + 2] + red[4 * t + 3];
    }
}

extern "C" void kernel_launch(void* const* d_in, const int* in_sizes, int n_in,
                              void* d_out, int out_size) {
    const float* psi = (const float*)d_in[0];
    const int*   inp = (const int*)d_in[1];
    const float* uth = (const float*)d_in[2];
    const float* nth = (const float*)d_in[3];
    float* out = (float*)d_out;

    float* probs_out = out;
    float* psi_out   = out + BATCH * 64;

    precompute_kernel<<<(STAGES * W_ * 1024 + 255) / 256, 256>>>(uth, nth);
    sim_kernel<<<BATCH, 256>>>(psi, inp, probs_out, psi_out);
}